// round 10
// baseline (speedup 1.0000x reference)
#include <cuda_runtime.h>
#include <cuda_bf16.h>
#include <math.h>
#include <stdint.h>

// ---------------------------------------------------------------------------
// Problem constants
// ---------------------------------------------------------------------------
#define N_ROWS 131072
#define D 64
#define K 512
#define KH 256                      // columns per CTA (K split in half)
#define TILE_M 128
#define NTILE_R (N_ROWS / TILE_M)   // 1024 row tiles
#define PADB 144                    // bf16 tile row stride in BYTES (64*2 + 16)

// Output layout: [xn | xn | proto | cvae | pdl]
#define XN2_OFF   ((long)N_ROWS * D)
#define PROTO_OFF (2L * N_ROWS * D)
#define CVAE_OFF  (PROTO_OFF + (long)N_ROWS * K)
#define PDL_OFF   (CVAE_OFF + 1)

// Shared memory layout (bytes) — per CTA, sized for 2 CTAs/SM
#define OFF_AHI   0                  // bf16 [128] rows x PADB
#define OFF_ALO   18432
#define OFF_WHI   36864              // bf16 [256] rows x PADB (this CTA's half)
#define OFF_WLO   73728
#define OFF_B2    110592             // f32 [256]
#define OFF_A2    111616             // f32 [128]
#define OFF_CMIN  112128             // u32 [256]  (persistent across tiles)
#define OFF_RMIN  113152             // u32 [128]  (per tile)
#define SMEM_TOTAL 113664            // 111 KB

// Device scratch (no allocations allowed)
__device__ unsigned int g_colmin[K];
__device__ unsigned int g_rowmin[N_ROWS];
__device__ float        g_b2[K];
__device__ unsigned int g_Whi_img[K * 32];   // packed bf16x2 [512][32]
__device__ unsigned int g_Wlo_img[K * 32];

// ---------------------------------------------------------------------------
// Helpers (sm_80-level PTX only: ldmatrix + mma.sync)
// ---------------------------------------------------------------------------
__device__ __forceinline__ uint32_t smem_u32(const void* p) {
    uint32_t a;
    asm("{ .reg .u64 t; cvta.to.shared.u64 t, %1; cvt.u32.u64 %0, t; }" : "=r"(a) : "l"(p));
    return a;
}
__device__ __forceinline__ void ldsm_x4(uint32_t* r, uint32_t addr) {
    asm volatile("ldmatrix.sync.aligned.m8n8.x4.shared.b16 {%0,%1,%2,%3}, [%4];"
                 : "=r"(r[0]), "=r"(r[1]), "=r"(r[2]), "=r"(r[3]) : "r"(addr));
}
__device__ __forceinline__ void mma_bf16(float* d, const uint32_t* a, uint32_t b0, uint32_t b1) {
    asm volatile("mma.sync.aligned.m16n8k16.row.col.f32.bf16.bf16.f32 "
                 "{%0,%1,%2,%3}, {%4,%5,%6,%7}, {%8,%9}, {%0,%1,%2,%3};"
                 : "+f"(d[0]), "+f"(d[1]), "+f"(d[2]), "+f"(d[3])
                 : "r"(a[0]), "r"(a[1]), "r"(a[2]), "r"(a[3]), "r"(b0), "r"(b1));
}

// ---------------------------------------------------------------------------
// Init: W -> packed bf16 hi/lo images + b2 + colmin/rowmin reset. 512 warps.
// ---------------------------------------------------------------------------
__global__ void swav_init_kernel(const float* __restrict__ W) {
    int gt  = blockIdx.x * blockDim.x + threadIdx.x;
    int r   = gt >> 5;
    int lid = gt & 31;

    // rowmin reset: 16384 threads x 8 = 131072
    #pragma unroll
    for (int i = 0; i < 8; ++i) g_rowmin[gt * 8 + i] = 0x7F800000u;

    if (r >= K) return;
    float2 v = *(const float2*)&W[r * D + lid * 2];
    __nv_bfloat16 h0 = __float2bfloat16(v.x);
    __nv_bfloat16 h1 = __float2bfloat16(v.y);
    float l0 = v.x - __bfloat162float(h0);
    float l1 = v.y - __bfloat162float(h1);
    __nv_bfloat162 hp = __nv_bfloat162(h0, h1);
    __nv_bfloat162 lp = __nv_bfloat162(__float2bfloat16(l0), __float2bfloat16(l1));

    g_Whi_img[r * 32 + lid] = *(unsigned int*)&hp;
    g_Wlo_img[r * 32 + lid] = *(unsigned int*)&lp;

    float s = fmaf(v.x, v.x, v.y * v.y);
    #pragma unroll
    for (int o = 16; o > 0; o >>= 1) s += __shfl_xor_sync(0xffffffffu, s, o);
    if (lid == 0) { g_b2[r] = s; g_colmin[r] = 0x7F800000u; }
}

// ---------------------------------------------------------------------------
// Main: PERSISTENT, COLUMN-SPLIT, occ 2. CTA owns 256 cols (ch = bid&1),
// strides row tiles. Per tile: LDG x -> normalize -> xn x2 (ch 0 only) ->
// bf16 hi/lo A tiles -> interleaved HMMA split GEMM (2 passes x 64 cols/warp)
// -> register epilogue (proto + z-mins) -> global row atomics.
// ---------------------------------------------------------------------------
__global__ __launch_bounds__(256, 2)
void swav_main_kernel(const float* __restrict__ x, float* __restrict__ out,
                      int nsm) {
    extern __shared__ __align__(16) char sm[];
    float*        b2s    = (float*)(sm + OFF_B2);
    float*        a2s    = (float*)(sm + OFF_A2);
    unsigned int* cmin_s = (unsigned int*)(sm + OFF_CMIN);
    unsigned int* rmin_s = (unsigned int*)(sm + OFF_RMIN);

    const uint32_t sb  = smem_u32(sm);
    const int t   = threadIdx.x;
    const int lid = t & 31;
    const int wid = t >> 5;
    const int ch  = blockIdx.x & 1;          // column half: cols [ch*256, +256)

    // ---- One-time: this CTA's W half -> padded smem; scalars ----
    {
        const uint4* whi = (const uint4*)(g_Whi_img + ch * (KH * 32));
        const uint4* wlo = (const uint4*)(g_Wlo_img + ch * (KH * 32));
        #pragma unroll
        for (int i = 0; i < 8; ++i) {
            int idx = t + i * 256;            // 2048 uint4
            int r = idx >> 3, c = idx & 7;
            *(uint4*)(sm + OFF_WHI + r * PADB + c * 16) = whi[idx];
            *(uint4*)(sm + OFF_WLO + r * PADB + c * 16) = wlo[idx];
        }
    }
    for (int i = t; i < KH; i += 256) {
        b2s[i] = g_b2[ch * KH + i];
        cmin_s[i] = 0x7F800000u;
    }

    // ldmatrix lane addressing (tile-invariant)
    const int wy = wid & 3, wx = wid >> 2;
    const int m0 = wy * 32;
    const uint32_t a_off    = (uint32_t)(m0 + (lid & 15)) * PADB + ((lid >> 4) * 16);
    const uint32_t aaddr_hi = sb + OFF_AHI + a_off;
    const uint32_t aaddr_lo = sb + OFF_ALO + a_off;
    const uint32_t b_rowi   = ((lid >> 4) << 3) + (lid & 7);
    const uint32_t b_koff   = ((lid >> 3) & 1) * 16;

    // ================= persistent row-tile loop =================
    for (int rt = blockIdx.x >> 1; rt < NTILE_R; rt += nsm) {
        const long row0 = (long)rt * TILE_M;

        __syncthreads();   // previous tile's ldsm reads complete -> A writable

        // ---- load x, normalize, write xn x2 (ch 0), build A hi/lo tiles ----
        {
            const float4* xg = (const float4*)(x + row0 * D);
            float4 v[8]; float s[8];
            #pragma unroll
            for (int i = 0; i < 8; ++i) {
                int idx = t + i * 256;                    // [128 rows][16 float4]
                v[i] = xg[idx];
                s[i] = fmaf(v[i].x, v[i].x, fmaf(v[i].y, v[i].y,
                        fmaf(v[i].z, v[i].z, v[i].w * v[i].w)));
            }
            #pragma unroll
            for (int m = 1; m < 16; m <<= 1)
                #pragma unroll
                for (int i = 0; i < 8; ++i)
                    s[i] += __shfl_xor_sync(0xffffffffu, s[i], m);

            float4* xn1 = (float4*)(out + row0 * D);
            float4* xn2 = (float4*)(out + XN2_OFF + row0 * D);
            #pragma unroll
            for (int i = 0; i < 8; ++i) {
                int idx = t + i * 256;
                int r = idx >> 4, c = idx & 15;
                float inv = 1.0f / fmaxf(sqrtf(s[i]), 1e-12f);
                float4 w4 = make_float4(v[i].x * inv, v[i].y * inv,
                                        v[i].z * inv, v[i].w * inv);
                if (ch == 0) { xn1[idx] = w4; xn2[idx] = w4; }
                if ((t & 15) == 0) a2s[r] = s[i] * inv * inv;

                __nv_bfloat16 hx = __float2bfloat16(w4.x), hy = __float2bfloat16(w4.y);
                __nv_bfloat16 hz = __float2bfloat16(w4.z), hw = __float2bfloat16(w4.w);
                __nv_bfloat162 hp0 = __nv_bfloat162(hx, hy);
                __nv_bfloat162 hp1 = __nv_bfloat162(hz, hw);
                __nv_bfloat162 lp0 = __nv_bfloat162(__float2bfloat16(w4.x - __bfloat162float(hx)),
                                                    __float2bfloat16(w4.y - __bfloat162float(hy)));
                __nv_bfloat162 lp1 = __nv_bfloat162(__float2bfloat16(w4.z - __bfloat162float(hz)),
                                                    __float2bfloat16(w4.w - __bfloat162float(hw)));
                uint2 hh = make_uint2(*(unsigned*)&hp0, *(unsigned*)&hp1);
                uint2 ll = make_uint2(*(unsigned*)&lp0, *(unsigned*)&lp1);
                *(uint2*)(sm + OFF_AHI + r * PADB + c * 8) = hh;
                *(uint2*)(sm + OFF_ALO + r * PADB + c * 8) = ll;
            }
        }
        if (t < TILE_M) rmin_s[t] = 0x7F800000u;
        __syncthreads();

        // ---- HMMA split GEMM + epilogue, 2 passes of 64 cols per warp ----
        float a2r[2][2];
        #pragma unroll
        for (int mf = 0; mf < 2; ++mf) {
            a2r[mf][0] = a2s[m0 + mf * 16 + (lid >> 2)];
            a2r[mf][1] = a2s[m0 + mf * 16 + (lid >> 2) + 8];
        }
        float rowmin[4];
        #pragma unroll
        for (int j = 0; j < 4; ++j) rowmin[j] = 3.0e38f;

        #pragma unroll 1
        for (int pass = 0; pass < 2; ++pass) {
            const int nb = wx * 128 + pass * 64;   // local col base (0..255)
            float acc[2][8][4];
            #pragma unroll
            for (int mf = 0; mf < 2; ++mf)
                #pragma unroll
                for (int p = 0; p < 8; ++p)
                    #pragma unroll
                    for (int q = 0; q < 4; ++q) acc[mf][p][q] = 0.f;

            #pragma unroll 1
            for (int k = 0; k < 4; ++k) {
                const uint32_t ka = (uint32_t)k * 32;
                uint32_t ah[2][4], al[2][4];
                ldsm_x4(ah[0], aaddr_hi + ka);
                ldsm_x4(ah[1], aaddr_hi + 16 * PADB + ka);
                ldsm_x4(al[0], aaddr_lo + ka);
                ldsm_x4(al[1], aaddr_lo + 16 * PADB + ka);
                #pragma unroll
                for (int p = 0; p < 4; ++p) {       // 16-col groups
                    uint32_t baddr = sb + OFF_WHI +
                        (uint32_t)(nb + p * 16 + b_rowi) * PADB + b_koff + ka;
                    uint32_t bh[4], bl[4];
                    ldsm_x4(bh, baddr);
                    ldsm_x4(bl, baddr + (OFF_WLO - OFF_WHI));
                    // Product-major interleave: 4 independent accumulator chains
                    mma_bf16(acc[0][2 * p],     ah[0], bh[0], bh[1]);   // hh
                    mma_bf16(acc[0][2 * p + 1], ah[0], bh[2], bh[3]);
                    mma_bf16(acc[1][2 * p],     ah[1], bh[0], bh[1]);
                    mma_bf16(acc[1][2 * p + 1], ah[1], bh[2], bh[3]);
                    mma_bf16(acc[0][2 * p],     ah[0], bl[0], bl[1]);   // hl
                    mma_bf16(acc[0][2 * p + 1], ah[0], bl[2], bl[3]);
                    mma_bf16(acc[1][2 * p],     ah[1], bl[0], bl[1]);
                    mma_bf16(acc[1][2 * p + 1], ah[1], bl[2], bl[3]);
                    mma_bf16(acc[0][2 * p],     al[0], bh[0], bh[1]);   // lh
                    mma_bf16(acc[0][2 * p + 1], al[0], bh[2], bh[3]);
                    mma_bf16(acc[1][2 * p],     al[1], bh[0], bh[1]);
                    mma_bf16(acc[1][2 * p + 1], al[1], bh[2], bh[3]);
                }
            }

            // Epilogue: proto stores + z-mins, all from registers
            #pragma unroll
            for (int p = 0; p < 8; ++p) {
                const int cl = nb + p * 8 + 2 * (lid & 3);   // local col
                const int cg = ch * KH + cl;                 // global col
                const float b2c0 = b2s[cl], b2c1 = b2s[cl + 1];
                float cm0 = 3.0e38f, cm1 = 3.0e38f;
                #pragma unroll
                for (int mf = 0; mf < 2; ++mf) {
                    float* d = acc[mf][p];
                    const int r0 = m0 + mf * 16 + (lid >> 2);
                    *(float2*)(out + PROTO_OFF + (row0 + r0) * (long)K + cg)
                        = make_float2(d[0], d[1]);
                    *(float2*)(out + PROTO_OFF + (row0 + r0 + 8) * (long)K + cg)
                        = make_float2(d[2], d[3]);
                    float z0 = fmaxf(fmaf(-2.f, d[0], a2r[mf][0] + b2c0), 0.f);
                    float z1 = fmaxf(fmaf(-2.f, d[1], a2r[mf][0] + b2c1), 0.f);
                    float z2 = fmaxf(fmaf(-2.f, d[2], a2r[mf][1] + b2c0), 0.f);
                    float z3 = fmaxf(fmaf(-2.f, d[3], a2r[mf][1] + b2c1), 0.f);
                    rowmin[mf * 2]     = fminf(rowmin[mf * 2],     fminf(z0, z1));
                    rowmin[mf * 2 + 1] = fminf(rowmin[mf * 2 + 1], fminf(z2, z3));
                    cm0 = fminf(cm0, fminf(z0, z2));
                    cm1 = fminf(cm1, fminf(z1, z3));
                }
                #pragma unroll
                for (int o = 4; o < 32; o <<= 1) {
                    cm0 = fminf(cm0, __shfl_xor_sync(0xffffffffu, cm0, o));
                    cm1 = fminf(cm1, __shfl_xor_sync(0xffffffffu, cm1, o));
                }
                if (lid < 4) {
                    atomicMin(&cmin_s[cl],     __float_as_uint(cm0));
                    atomicMin(&cmin_s[cl + 1], __float_as_uint(cm1));
                }
            }
        }

        // Row-min: quad reduce -> smem -> global
        #pragma unroll
        for (int o = 1; o < 4; o <<= 1)
            #pragma unroll
            for (int j = 0; j < 4; ++j)
                rowmin[j] = fminf(rowmin[j], __shfl_xor_sync(0xffffffffu, rowmin[j], o));
        if ((lid & 3) == 0) {
            const int rq = lid >> 2;
            atomicMin(&rmin_s[m0 + rq],      __float_as_uint(rowmin[0]));
            atomicMin(&rmin_s[m0 + rq + 8],  __float_as_uint(rowmin[1]));
            atomicMin(&rmin_s[m0 + 16 + rq], __float_as_uint(rowmin[2]));
            atomicMin(&rmin_s[m0 + 24 + rq], __float_as_uint(rowmin[3]));
        }
        __syncthreads();
        if (t < TILE_M)
            atomicMin(&g_rowmin[row0 + t], rmin_s[t]);
    }

    // ---- merge per-CTA column mins into global (once) ----
    if (t < KH)
        atomicMin(&g_colmin[ch * KH + t], cmin_s[t]);
}

// ---------------------------------------------------------------------------
// Final: deterministic reductions + scalar outputs
// ---------------------------------------------------------------------------
__global__ void swav_final_kernel(const float* __restrict__ recon,
                                  const float* __restrict__ kl,
                                  const float* __restrict__ mmd,
                                  float* __restrict__ out) {
    __shared__ float red[K];
    int t = threadIdx.x;  // 512 threads
    float s = 0.f;
    for (int i = t; i < N_ROWS; i += K)
        s += sqrtf(fmaxf(__uint_as_float(g_rowmin[i]), 1e-12f));
    red[t] = s;
    __syncthreads();
    for (int st = 256; st > 0; st >>= 1) { if (t < st) red[t] += red[t + st]; __syncthreads(); }
    float rowsum = red[0];
    __syncthreads();

    red[t] = sqrtf(fmaxf(__uint_as_float(g_colmin[t]), 1e-12f));
    __syncthreads();
    for (int st = 256; st > 0; st >>= 1) { if (t < st) red[t] += red[t + st]; __syncthreads(); }

    if (t == 0) {
        float pdl = 0.5f * (rowsum / (float)N_ROWS) + 0.5f * (red[0] / (float)K);
        out[CVAE_OFF] = recon[0] + 0.5f * kl[0] + mmd[0];
        out[PDL_OFF]  = pdl;
    }
}

// ---------------------------------------------------------------------------
extern "C" void kernel_launch(void* const* d_in, const int* in_sizes, int n_in,
                              void* d_out, int out_size) {
    const float* x     = (const float*)d_in[0];
    const float* W     = (const float*)d_in[1];
    const float* recon = (const float*)d_in[2];
    const float* kl    = (const float*)d_in[3];
    const float* mmd   = (const float*)d_in[4];
    float* out = (float*)d_out;

    static int nsm = 0;
    if (nsm == 0) {
        cudaDeviceGetAttribute(&nsm, cudaDevAttrMultiProcessorCount, 0);
        if (nsm <= 0) nsm = 148;
        cudaFuncSetAttribute(swav_main_kernel,
                             cudaFuncAttributeMaxDynamicSharedMemorySize, SMEM_TOTAL);
    }

    swav_init_kernel<<<64, 256>>>(W);
    swav_main_kernel<<<2 * nsm, 256, SMEM_TOTAL>>>(x, out, nsm);
    swav_final_kernel<<<1, K>>>(recon, kl, mmd, out);
}

// round 12
// speedup vs baseline: 1.9803x; 1.9803x over previous
#include <cuda_runtime.h>
#include <cuda_fp16.h>
#include <math.h>
#include <stdint.h>

// ---------------------------------------------------------------------------
// Problem constants
// ---------------------------------------------------------------------------
#define N_ROWS 131072
#define D 64
#define K 512
#define TILE_M 128
#define NTILES (N_ROWS / TILE_M)    // 1024
#define PADB 144                    // fp16 tile row stride in BYTES (64*2 + 16)

// Output layout: [xn | xn | proto | cvae | pdl]
#define XN2_OFF   ((long)N_ROWS * D)
#define PROTO_OFF (2L * N_ROWS * D)
#define CVAE_OFF  (PROTO_OFF + (long)N_ROWS * K)
#define PDL_OFF   (CVAE_OFF + 1)

// Shared memory layout (bytes)
#define OFF_AHI   0                  // fp16 [128] rows x PADB (hi only!)
#define OFF_WHI   18432              // fp16 [512] rows x PADB (resident)
#define OFF_WLO   92160
#define OFF_B2    165888             // f32 [512]
#define OFF_A2    167936             // f32 [128]
#define OFF_CMIN  168448             // u32 [512]  (persistent across tiles)
#define OFF_RMIN  170496             // u32 [128]  (per tile)
#define OFF_RED   171008             // f32 [128]
#define OFF_XS    171520             // f32 x staging [128][64] = 32768 (cp.async)
#define SMEM_TOTAL 204288

// Device scratch (no allocations allowed)
__device__ unsigned int g_colmin[K];
__device__ float        g_row_partial[NTILES];
__device__ float        g_b2[K];
__device__ unsigned int g_Whi_img[K * 32];   // packed fp16x2 [512][32]
__device__ unsigned int g_Wlo_img[K * 32];

// ---------------------------------------------------------------------------
// Helpers (sm_80-level PTX only: ldmatrix + mma.sync + cp.async)
// ---------------------------------------------------------------------------
__device__ __forceinline__ uint32_t smem_u32(const void* p) {
    uint32_t a;
    asm("{ .reg .u64 t; cvta.to.shared.u64 t, %1; cvt.u32.u64 %0, t; }" : "=r"(a) : "l"(p));
    return a;
}
__device__ __forceinline__ void ldsm_x4(uint32_t* r, uint32_t addr) {
    asm volatile("ldmatrix.sync.aligned.m8n8.x4.shared.b16 {%0,%1,%2,%3}, [%4];"
                 : "=r"(r[0]), "=r"(r[1]), "=r"(r[2]), "=r"(r[3]) : "r"(addr));
}
__device__ __forceinline__ void mma_f16(float* d, const uint32_t* a, uint32_t b0, uint32_t b1) {
    asm volatile("mma.sync.aligned.m16n8k16.row.col.f32.f16.f16.f32 "
                 "{%0,%1,%2,%3}, {%4,%5,%6,%7}, {%8,%9}, {%0,%1,%2,%3};"
                 : "+f"(d[0]), "+f"(d[1]), "+f"(d[2]), "+f"(d[3])
                 : "r"(a[0]), "r"(a[1]), "r"(a[2]), "r"(a[3]), "r"(b0), "r"(b1));
}
__device__ __forceinline__ void cp_async16(uint32_t saddr, const void* gptr) {
    asm volatile("cp.async.cg.shared.global [%0], [%1], 16;"
                 :: "r"(saddr), "l"(gptr) : "memory");
}
#define CP_COMMIT()   asm volatile("cp.async.commit_group;" ::: "memory")
#define CP_WAIT_ALL() asm volatile("cp.async.wait_all;" ::: "memory")

// ---------------------------------------------------------------------------
// Init: W -> packed fp16 hi/lo images + b2 + colmin reset. 512 warps.
// ---------------------------------------------------------------------------
__global__ void swav_init_kernel(const float* __restrict__ W) {
    int gt  = blockIdx.x * blockDim.x + threadIdx.x;
    int r   = gt >> 5;
    int lid = gt & 31;
    if (r >= K) return;

    float2 v = *(const float2*)&W[r * D + lid * 2];
    __half h0 = __float2half_rn(v.x);
    __half h1 = __float2half_rn(v.y);
    float l0 = v.x - __half2float(h0);
    float l1 = v.y - __half2float(h1);
    __half2 hp = __halves2half2(h0, h1);
    __half2 lp = __halves2half2(__float2half_rn(l0), __float2half_rn(l1));

    g_Whi_img[r * 32 + lid] = *(unsigned int*)&hp;
    g_Wlo_img[r * 32 + lid] = *(unsigned int*)&lp;

    float s = fmaf(v.x, v.x, v.y * v.y);
    #pragma unroll
    for (int o = 16; o > 0; o >>= 1) s += __shfl_xor_sync(0xffffffffu, s, o);
    if (lid == 0) { g_b2[r] = s; g_colmin[r] = 0x7F800000u; }
}

// ---------------------------------------------------------------------------
// Main: PERSISTENT CTAs. W (fp16 hi/lo) resident in smem; x staged via
// cp.async. Per tile: normalize -> xn x2 -> fp16 A-hi tile -> interleaved
// 2-product HMMA GEMM (xh*wh + xh*wl) -> register epilogue -> row reduce.
// ---------------------------------------------------------------------------
__global__ __launch_bounds__(256, 1)
void swav_main_kernel(const float* __restrict__ x, float* __restrict__ out,
                      int nsm) {
    extern __shared__ __align__(16) char sm[];
    float*        b2s    = (float*)(sm + OFF_B2);
    float*        a2s    = (float*)(sm + OFF_A2);
    unsigned int* cmin_s = (unsigned int*)(sm + OFF_CMIN);
    unsigned int* rmin_s = (unsigned int*)(sm + OFF_RMIN);
    float*        red    = (float*)(sm + OFF_RED);

    const uint32_t sb  = smem_u32(sm);
    const int t   = threadIdx.x;
    const int lid = t & 31;
    const int wid = t >> 5;

    // ---- One-time: W images -> padded smem tiles; scalars; first x prefetch ----
    {
        const uint4* whi = (const uint4*)g_Whi_img;   // [512*8] uint4
        const uint4* wlo = (const uint4*)g_Wlo_img;
        #pragma unroll
        for (int i = 0; i < 16; ++i) {
            int idx = t + i * 256;            // 4096 uint4
            int r = idx >> 3, c = idx & 7;
            *(uint4*)(sm + OFF_WHI + r * PADB + c * 16) = whi[idx];
            *(uint4*)(sm + OFF_WLO + r * PADB + c * 16) = wlo[idx];
        }
    }
    for (int i = t; i < K; i += 256) { b2s[i] = g_b2[i]; cmin_s[i] = 0x7F800000u; }

    // Prefetch x for first tile
    {
        int tile0 = blockIdx.x;
        if (tile0 < NTILES) {
            const char* gx = (const char*)(x + (long)tile0 * TILE_M * D);
            #pragma unroll
            for (int i = 0; i < 8; ++i) {
                int idx = t + i * 256;
                cp_async16(sb + OFF_XS + idx * 16, gx + (long)idx * 16);
            }
        }
        CP_COMMIT();
    }

    // ldmatrix lane addressing (tile-invariant)
    const int wy = wid & 3, wx = wid >> 2;
    const int m0 = wy * 32;
    const uint32_t a_off    = (uint32_t)(m0 + (lid & 15)) * PADB + ((lid >> 4) * 16);
    const uint32_t aaddr_hi = sb + OFF_AHI + a_off;
    const uint32_t b_rowi   = ((lid >> 4) << 3) + (lid & 7);
    const uint32_t b_koff   = ((lid >> 3) & 1) * 16;

    // ================= persistent tile loop =================
    for (int tile = blockIdx.x; tile < NTILES; tile += nsm) {
        const long row0 = (long)tile * TILE_M;

        CP_WAIT_ALL();
        __syncthreads();

        // ---- read staged x into regs ----
        float4 v[8]; float s[8];
        #pragma unroll
        for (int i = 0; i < 8; ++i) {
            int idx = t + i * 256;                    // [128 rows][16 float4]
            v[i] = *(const float4*)(sm + OFF_XS + idx * 16);
            s[i] = fmaf(v[i].x, v[i].x, fmaf(v[i].y, v[i].y,
                    fmaf(v[i].z, v[i].z, v[i].w * v[i].w)));
        }
        __syncthreads();   // staging consumed -> safe to overwrite

        // ---- prefetch next tile's x (overlaps with pack + GEMM) ----
        {
            int nxt = tile + nsm;
            if (nxt < NTILES) {
                const char* gx = (const char*)(x + (long)nxt * TILE_M * D);
                #pragma unroll
                for (int i = 0; i < 8; ++i) {
                    int idx = t + i * 256;
                    cp_async16(sb + OFF_XS + idx * 16, gx + (long)idx * 16);
                }
            }
            CP_COMMIT();
        }

        // ---- normalize, write xn x2, build A hi tile (fp16) ----
        #pragma unroll
        for (int m = 1; m < 16; m <<= 1)
            #pragma unroll
            for (int i = 0; i < 8; ++i)
                s[i] += __shfl_xor_sync(0xffffffffu, s[i], m);
        {
            float4* xn1 = (float4*)(out + row0 * D);
            float4* xn2 = (float4*)(out + XN2_OFF + row0 * D);
            #pragma unroll
            for (int i = 0; i < 8; ++i) {
                int idx = t + i * 256;
                int r = idx >> 4, c = idx & 15;
                float inv = 1.0f / fmaxf(sqrtf(s[i]), 1e-12f);
                float4 w4 = make_float4(v[i].x * inv, v[i].y * inv,
                                        v[i].z * inv, v[i].w * inv);
                xn1[idx] = w4;
                xn2[idx] = w4;
                if ((t & 15) == 0) a2s[r] = s[i] * inv * inv;

                __half2 hp0 = __floats2half2_rn(w4.x, w4.y);
                __half2 hp1 = __floats2half2_rn(w4.z, w4.w);
                uint2 hh = make_uint2(*(unsigned*)&hp0, *(unsigned*)&hp1);
                *(uint2*)(sm + OFF_AHI + r * PADB + c * 8) = hh;
            }
        }
        if (t < TILE_M) rmin_s[t] = 0x7F800000u;
        __syncthreads();

        // ---- 2-product HMMA GEMM + epilogue, two column halves ----
        float a2r[2][2];
        #pragma unroll
        for (int mf = 0; mf < 2; ++mf) {
            a2r[mf][0] = a2s[m0 + mf * 16 + (lid >> 2)];
            a2r[mf][1] = a2s[m0 + mf * 16 + (lid >> 2) + 8];
        }
        float rowmin[4];
        #pragma unroll
        for (int j = 0; j < 4; ++j) rowmin[j] = 3.0e38f;

        for (int h = 0; h < 2; ++h) {
            const int nb = h * 256 + wx * 128;
            float acc[2][16][4];
            #pragma unroll
            for (int mf = 0; mf < 2; ++mf)
                #pragma unroll
                for (int p = 0; p < 16; ++p)
                    #pragma unroll
                    for (int q = 0; q < 4; ++q) acc[mf][p][q] = 0.f;

            #pragma unroll 1
            for (int k = 0; k < 4; ++k) {
                const uint32_t ka = (uint32_t)k * 32;
                uint32_t ah[2][4];
                ldsm_x4(ah[0], aaddr_hi + ka);
                ldsm_x4(ah[1], aaddr_hi + 16 * PADB + ka);
                #pragma unroll
                for (int p = 0; p < 8; ++p) {
                    uint32_t baddr = sb + OFF_WHI +
                        (uint32_t)(nb + p * 16 + b_rowi) * PADB + b_koff + ka;
                    uint32_t bh[4], bl[4];
                    ldsm_x4(bh, baddr);
                    ldsm_x4(bl, baddr + (OFF_WLO - OFF_WHI));
                    // Product-major interleave: 4 independent accumulator
                    // chains; each chain's 2 dependent MMAs 4 slots apart.
                    mma_f16(acc[0][2 * p],     ah[0], bh[0], bh[1]);   // hh
                    mma_f16(acc[0][2 * p + 1], ah[0], bh[2], bh[3]);
                    mma_f16(acc[1][2 * p],     ah[1], bh[0], bh[1]);
                    mma_f16(acc[1][2 * p + 1], ah[1], bh[2], bh[3]);
                    mma_f16(acc[0][2 * p],     ah[0], bl[0], bl[1]);   // hl
                    mma_f16(acc[0][2 * p + 1], ah[0], bl[2], bl[3]);
                    mma_f16(acc[1][2 * p],     ah[1], bl[0], bl[1]);
                    mma_f16(acc[1][2 * p + 1], ah[1], bl[2], bl[3]);
                }
            }

            // Epilogue: proto stores + z-mins, all from registers
            #pragma unroll
            for (int p = 0; p < 16; ++p) {
                const int c = nb + p * 8 + 2 * (lid & 3);
                const float b2c0 = b2s[c], b2c1 = b2s[c + 1];
                float cm0 = 3.0e38f, cm1 = 3.0e38f;
                #pragma unroll
                for (int mf = 0; mf < 2; ++mf) {
                    float* d = acc[mf][p];
                    const int r0 = m0 + mf * 16 + (lid >> 2);
                    *(float2*)(out + PROTO_OFF + (row0 + r0) * (long)K + c)
                        = make_float2(d[0], d[1]);
                    *(float2*)(out + PROTO_OFF + (row0 + r0 + 8) * (long)K + c)
                        = make_float2(d[2], d[3]);
                    float z0 = fmaxf(fmaf(-2.f, d[0], a2r[mf][0] + b2c0), 0.f);
                    float z1 = fmaxf(fmaf(-2.f, d[1], a2r[mf][0] + b2c1), 0.f);
                    float z2 = fmaxf(fmaf(-2.f, d[2], a2r[mf][1] + b2c0), 0.f);
                    float z3 = fmaxf(fmaf(-2.f, d[3], a2r[mf][1] + b2c1), 0.f);
                    rowmin[mf * 2]     = fminf(rowmin[mf * 2],     fminf(z0, z1));
                    rowmin[mf * 2 + 1] = fminf(rowmin[mf * 2 + 1], fminf(z2, z3));
                    cm0 = fminf(cm0, fminf(z0, z2));
                    cm1 = fminf(cm1, fminf(z1, z3));
                }
                #pragma unroll
                for (int o = 4; o < 32; o <<= 1) {
                    cm0 = fminf(cm0, __shfl_xor_sync(0xffffffffu, cm0, o));
                    cm1 = fminf(cm1, __shfl_xor_sync(0xffffffffu, cm1, o));
                }
                if (lid < 4) {
                    atomicMin(&cmin_s[c],     __float_as_uint(cm0));
                    atomicMin(&cmin_s[c + 1], __float_as_uint(cm1));
                }
            }
        }

        // Row-min: quad reduce then smem atomics
        #pragma unroll
        for (int o = 1; o < 4; o <<= 1)
            #pragma unroll
            for (int j = 0; j < 4; ++j)
                rowmin[j] = fminf(rowmin[j], __shfl_xor_sync(0xffffffffu, rowmin[j], o));
        if ((lid & 3) == 0) {
            const int rq = lid >> 2;
            atomicMin(&rmin_s[m0 + rq],      __float_as_uint(rowmin[0]));
            atomicMin(&rmin_s[m0 + rq + 8],  __float_as_uint(rowmin[1]));
            atomicMin(&rmin_s[m0 + 16 + rq], __float_as_uint(rowmin[2]));
            atomicMin(&rmin_s[m0 + 24 + rq], __float_as_uint(rowmin[3]));
        }
        __syncthreads();

        // Per-tile row reduction -> g_row_partial[tile]
        if (t < TILE_M)
            red[t] = sqrtf(fmaxf(__uint_as_float(rmin_s[t]), 1e-12f));
        __syncthreads();
        for (int st = 64; st > 0; st >>= 1) {
            if (t < st) red[t] += red[t + st];
            __syncthreads();
        }
        if (t == 0) g_row_partial[tile] = red[0];
        __syncthreads();
    }

    // ---- merge per-CTA column mins into global (once) ----
    atomicMin(&g_colmin[t],       cmin_s[t]);
    atomicMin(&g_colmin[t + 256], cmin_s[t + 256]);
}

// ---------------------------------------------------------------------------
// Final: deterministic reductions + scalar outputs
// ---------------------------------------------------------------------------
__global__ void swav_final_kernel(const float* __restrict__ recon,
                                  const float* __restrict__ kl,
                                  const float* __restrict__ mmd,
                                  float* __restrict__ out) {
    __shared__ float red[K];
    int t = threadIdx.x;  // 512 threads
    float s = 0.f;
    for (int i = t; i < NTILES; i += K) s += g_row_partial[i];
    red[t] = s;
    __syncthreads();
    for (int st = 256; st > 0; st >>= 1) { if (t < st) red[t] += red[t + st]; __syncthreads(); }
    float rowsum = red[0];
    __syncthreads();

    red[t] = sqrtf(fmaxf(__uint_as_float(g_colmin[t]), 1e-12f));
    __syncthreads();
    for (int st = 256; st > 0; st >>= 1) { if (t < st) red[t] += red[t + st]; __syncthreads(); }

    if (t == 0) {
        float pdl = 0.5f * (rowsum / (float)N_ROWS) + 0.5f * (red[0] / (float)K);
        out[CVAE_OFF] = recon[0] + 0.5f * kl[0] + mmd[0];
        out[PDL_OFF]  = pdl;
    }
}

// ---------------------------------------------------------------------------
extern "C" void kernel_launch(void* const* d_in, const int* in_sizes, int n_in,
                              void* d_out, int out_size) {
    const float* x     = (const float*)d_in[0];
    const float* W     = (const float*)d_in[1];
    const float* recon = (const float*)d_in[2];
    const float* kl    = (const float*)d_in[3];
    const float* mmd   = (const float*)d_in[4];
    float* out = (float*)d_out;

    static int nsm = 0;
    if (nsm == 0) {
        cudaDeviceGetAttribute(&nsm, cudaDevAttrMultiProcessorCount, 0);
        if (nsm <= 0) nsm = 148;
        cudaFuncSetAttribute(swav_main_kernel,
                             cudaFuncAttributeMaxDynamicSharedMemorySize, SMEM_TOTAL);
    }

    swav_init_kernel<<<64, 256>>>(W);
    swav_main_kernel<<<nsm, 256, SMEM_TOTAL>>>(x, out, nsm);
    swav_final_kernel<<<1, K>>>(recon, kl, mmd, out);
}